// round 16
// baseline (speedup 1.0000x reference)
#include <cuda_runtime.h>
#include <cuda_bf16.h>
#include <math.h>

// ---------------- problem constants ----------------
#define CHN   256
#define HWD   96
#define KS    8
#define STRD  3
#define VCN   512
#define OHW   30            // (96-8)/3+1
#define LPB   900           // 30*30
#define NPAT  7200          // 8*900
#define KK2   64            // 8*8
#define PPAD  260           // padded row stride (stride%32==4 -> LDS.128 conflict-free in 8-lane phases)
#define VCHUNK 128          // v per smem chunk
#define NCHUNK 4            // 512/128
#define D1    768           // 3*CH
#define D0    320           // CH + kk

// scratch (device globals: allocation-free)
__device__ float g_inv_wn[VCN];
__device__ float g_inp[(size_t)NPAT * D0];   // 9.2 MB
__device__ float g_h1 [(size_t)NPAT * D1];   // 22.1 MB

// ---------------- packed fp32x2 helpers ----------------
__device__ __forceinline__ unsigned long long ffma2(unsigned long long a,
                                                    unsigned long long b,
                                                    unsigned long long c) {
    unsigned long long d;
    asm("fma.rn.f32x2 %0, %1, %2, %3;" : "=l"(d) : "l"(a), "l"(b), "l"(c));
    return d;
}
__device__ __forceinline__ float f2sum(unsigned long long v) {
    float lo, hi;
    asm("mov.b64 {%0, %1}, %2;" : "=f"(lo), "=f"(hi) : "l"(v));
    return lo + hi;
}

// ---------------- kernel W: inverse weight norms ----------------
__global__ void wnorm_kernel(const float* __restrict__ cw) {
    int v = threadIdx.x;                  // 512 threads, 1 block
    const float* r = cw + (size_t)v * CHN;
    float s = 0.f;
    #pragma unroll 8
    for (int c = 0; c < CHN; c++) { float w = r[c]; s += w * w; }
    g_inv_wn[v] = 1.0f / sqrtf(s);
}

// ---------------- kernel A: per-patch cosine sim + argmax + feature build ----------------
// grid = 7200 blocks, 256 threads. Dynamic smem ~202 KB.
// Main-loop mapping: warp w owns s-tile [8w, 8w+8) (register accumulators),
// lane ln owns v = chunk*128 + vh*32 + ln for vh in 0..3.
// Patch operand loads are uniform-address broadcasts (1 wavefront each);
// weight loads are lane-unique conflict-free LDS.128.
__global__ __launch_bounds__(256, 1)
void patch_kernel(const float* __restrict__ x, const float* __restrict__ cw) {
    extern __shared__ float sm[];
    float* p_sm   = sm;                         // [64][PPAD]
    float* w_sm   = sm + KK2 * PPAD;            // [128][PPAD]
    float* inv_xn = w_sm + VCHUNK * PPAD;       // [64]
    float* red_val = inv_xn + 64;               // [256]
    int*   red_idx = (int*)(red_val + 256);     // [256]

    const int t = threadIdx.x;
    const int n = blockIdx.x;
    const int b  = n / LPB;
    const int l  = n - b * LPB;
    const int oy = l / OHW;
    const int ox = l - oy * OHW;

    const float* xb = x + ((size_t)b * CHN) * (HWD * HWD) + (oy * STRD) * HWD + (ox * STRD);

    // ---- load patch: 2048 (c,kh) rows of 8 contiguous floats; 8 rows/thread ----
    #pragma unroll
    for (int i = 0; i < 8; i++) {
        int r  = t + 256 * i;
        int c  = r >> 3;
        int kh = r & 7;
        const float* src = xb + (size_t)c * (HWD * HWD) + kh * HWD;
        float* dst = p_sm + c;
        #pragma unroll
        for (int kw = 0; kw < 8; kw++)
            dst[(kh * 8 + kw) * PPAD] = src[kw];
    }
    __syncthreads();

    // ---- x_norm: 4 partial sums per s ----
    {
        int s = t & 63, part = t >> 6;
        const float* pr = p_sm + s * PPAD + part * 64;
        float a = 0.f;
        #pragma unroll 8
        for (int i = 0; i < 64; i++) { float v = pr[i]; a += v * v; }
        red_val[t] = a;
    }
    __syncthreads();
    if (t < 64) {
        float ss = red_val[t] + red_val[t + 64] + red_val[t + 128] + red_val[t + 192];
        inv_xn[t] = 1.0f / sqrtf(ss);
    }

    // ---- main streaming GEMM + argmax ----
    const int w  = t >> 5;                 // warp id -> s-tile
    const int ln = t & 31;                 // lane -> v within chunk
    const float* p_base = p_sm + (w * 8) * PPAD;
    const float* wr0    = w_sm + ln * PPAD;

    float bestv = -1e30f;
    int   besti = 0;

    for (int ch = 0; ch < NCHUNK; ch++) {
        __syncthreads();  // w_sm readers of previous chunk done; inv_xn visible on first pass
        // stage 128 x 256 weight chunk (coalesced)
        {
            const float* wsrc = cw + (size_t)(ch * VCHUNK) * CHN;
            #pragma unroll 4
            for (int i = 0; i < 128; i++) {
                int idx = t + 256 * i;           // 0..32767
                int vl = idx >> 8, c = idx & 255;
                w_sm[vl * PPAD + c] = wsrc[idx];
            }
        }
        __syncthreads();

        unsigned long long acc[8][4];
        #pragma unroll
        for (int s = 0; s < 8; s++)
            #pragma unroll
            for (int vh = 0; vh < 4; vh++) acc[s][vh] = 0ull;

        #pragma unroll 2
        for (int c = 0; c < CHN; c += 4) {
            ulonglong2 wv0 = *reinterpret_cast<const ulonglong2*>(wr0 + c);
            ulonglong2 wv1 = *reinterpret_cast<const ulonglong2*>(wr0 + 32 * PPAD + c);
            ulonglong2 wv2 = *reinterpret_cast<const ulonglong2*>(wr0 + 64 * PPAD + c);
            ulonglong2 wv3 = *reinterpret_cast<const ulonglong2*>(wr0 + 96 * PPAD + c);
            #pragma unroll
            for (int s = 0; s < 8; s++) {
                ulonglong2 pv = *reinterpret_cast<const ulonglong2*>(p_base + s * PPAD + c); // broadcast
                acc[s][0] = ffma2(pv.x, wv0.x, acc[s][0]);
                acc[s][0] = ffma2(pv.y, wv0.y, acc[s][0]);
                acc[s][1] = ffma2(pv.x, wv1.x, acc[s][1]);
                acc[s][1] = ffma2(pv.y, wv1.y, acc[s][1]);
                acc[s][2] = ffma2(pv.x, wv2.x, acc[s][2]);
                acc[s][2] = ffma2(pv.y, wv2.y, acc[s][2]);
                acc[s][3] = ffma2(pv.x, wv3.x, acc[s][3]);
                acc[s][3] = ffma2(pv.y, wv3.y, acc[s][3]);
            }
        }

        #pragma unroll
        for (int vh = 0; vh < 4; vh++) {
            int v = ch * VCHUNK + vh * 32 + ln;
            float iw = g_inv_wn[v];
            #pragma unroll
            for (int s = 0; s < 8; s++) {
                int sg = w * 8 + s;
                float y = f2sum(acc[s][vh]) * inv_xn[sg] * iw;
                int gi = v * KK2 + sg;
                if (y > bestv || (y == bestv && gi < besti)) { bestv = y; besti = gi; }
            }
        }
    }

    // ---- block argmax reduction (tie -> smallest idx, matches jnp.argmax) ----
    __syncthreads();
    red_val[t] = bestv; red_idx[t] = besti;
    __syncthreads();
    #pragma unroll
    for (int off = 128; off > 0; off >>= 1) {
        if (t < off) {
            float v2 = red_val[t + off]; int i2 = red_idx[t + off];
            if (v2 > red_val[t] || (v2 == red_val[t] && i2 < red_idx[t])) {
                red_val[t] = v2; red_idx[t] = i2;
            }
        }
        __syncthreads();
    }
    const float max_sim = red_val[0];
    const int   idx     = red_idx[0];
    const int   max_ch  = idx >> 6;
    const int   col     = idx & 63;

    // ---- sim_map_max: recompute y[max_ch][s] for all s ----
    float partial;
    {
        int s = t & 63, part = t >> 6;
        const float* pr = p_sm + s * PPAD + part * 64;
        const float* wr = cw + (size_t)max_ch * CHN + part * 64;
        float a = 0.f;
        #pragma unroll 8
        for (int i = 0; i < 64; i++) a += pr[i] * wr[i];
        partial = a;
    }
    __syncthreads();           // everyone has read red_val[0]/red_idx[0]
    red_val[t] = partial;
    __syncthreads();

    float* inp_row = g_inp + (size_t)n * D0;
    const float iwmax = g_inv_wn[max_ch];
    if (t < 64) {
        float d = red_val[t] + red_val[t + 64] + red_val[t + 128] + red_val[t + 192];
        inp_row[CHN + t] = d * inv_xn[t] * iwmax;
    }

    // ---- integ: max_act * max_sim + w[max_ch] * (1 - max_sim) ----
    {
        float pa = p_sm[col * PPAD + t];                  // t == channel
        float wv = cw[(size_t)max_ch * CHN + t];
        inp_row[t] = pa * max_sim + wv * (1.0f - max_sim);
    }
}

// ---------------- tiled SGEMM for the MLP: C = act(A * B^T + bias) ----------------
// A: [M][KD] row-major, B: [NC][KD] row-major (so inner product of rows).
// Block tile 64x64, thread micro-tile 4x4, 256 threads.
template <int KD, int ACT>
__device__ __forceinline__ void gemm_body(const float* __restrict__ A,
                                          const float* __restrict__ B,
                                          const float* __restrict__ bias,
                                          float* __restrict__ C,
                                          int M, int NC) {
    __shared__ float As[32][68];
    __shared__ float Bs[32][68];
    const int t  = threadIdx.x;
    const int tx = t & 15;     // n
    const int ty = t >> 4;     // m
    const int m0 = blockIdx.x * 64;
    const int n0 = blockIdx.y * 64;

    float acc[4][4] = {};

    for (int k0 = 0; k0 < KD; k0 += 32) {
        #pragma unroll
        for (int i = 0; i < 8; i++) {
            int e  = t + 256 * i;
            int mr = e >> 5, kc = e & 31;
            int mg = m0 + mr;
            As[kc][mr] = (mg < M) ? A[(size_t)mg * KD + k0 + kc] : 0.0f;
            int og = n0 + mr;                         // N tiles always divide
            Bs[kc][mr] = B[(size_t)og * KD + k0 + kc];
        }
        __syncthreads();
        #pragma unroll 8
        for (int kk = 0; kk < 32; kk++) {
            float4 av = *reinterpret_cast<const float4*>(&As[kk][ty * 4]);
            float4 bv = *reinterpret_cast<const float4*>(&Bs[kk][tx * 4]);
            float a[4] = {av.x, av.y, av.z, av.w};
            float bb[4] = {bv.x, bv.y, bv.z, bv.w};
            #pragma unroll
            for (int i = 0; i < 4; i++)
                #pragma unroll
                for (int j = 0; j < 4; j++)
                    acc[i][j] += a[i] * bb[j];
        }
        __syncthreads();
    }

    #pragma unroll
    for (int i = 0; i < 4; i++) {
        int mg = m0 + ty * 4 + i;
        if (mg >= M) continue;
        #pragma unroll
        for (int j = 0; j < 4; j++) {
            int og = n0 + tx * 4 + j;
            float v = acc[i][j] + bias[og];
            if (ACT == 0) v = (v > 0.f) ? v : 0.2f * v;     // leaky relu
            else          v = tanhf(v);
            C[(size_t)mg * NC + og] = v;
        }
    }
}

__global__ __launch_bounds__(256)
void gemm1_kernel(const float* __restrict__ W1, const float* __restrict__ b1) {
    gemm_body<D0, 0>(g_inp, W1, b1, g_h1, NPAT, D1);
}

__global__ __launch_bounds__(256)
void gemm2_kernel(const float* __restrict__ W2, const float* __restrict__ b2,
                  float* __restrict__ out) {
    gemm_body<D1, 1>(g_h1, W2, b2, out, NPAT, CHN);
}

// ---------------- launch ----------------
extern "C" void kernel_launch(void* const* d_in, const int* in_sizes, int n_in,
                              void* d_out, int out_size) {
    const float* x   = (const float*)d_in[0];
    const float* cw  = (const float*)d_in[1];
    const float* W1  = (const float*)d_in[2];
    const float* b1  = (const float*)d_in[3];
    const float* W2  = (const float*)d_in[4];
    const float* b2  = (const float*)d_in[5];
    float* out = (float*)d_out;

    const int smemA = (KK2 * PPAD + VCHUNK * PPAD + 64 + 256 + 256 + 8) * 4;  // ~202 KB
    cudaFuncSetAttribute(patch_kernel, cudaFuncAttributeMaxDynamicSharedMemorySize, smemA);

    wnorm_kernel<<<1, VCN>>>(cw);
    patch_kernel<<<NPAT, 256, smemA>>>(x, cw);
    gemm1_kernel<<<dim3((NPAT + 63) / 64, D1 / 64), 256>>>(W1, b1);
    gemm2_kernel<<<dim3((NPAT + 63) / 64, CHN / 64), 256>>>(W2, b2, out);
}

// round 17
// speedup vs baseline: 1.0033x; 1.0033x over previous
#include <cuda_runtime.h>
#include <cuda_bf16.h>
#include <math.h>

// ---------------- problem constants ----------------
#define CHN   256
#define HWD   96
#define KS    8
#define STRD  3
#define VCN   512
#define OHW   30            // (96-8)/3+1
#define LPB   900           // 30*30
#define NPAT  7200          // 8*900
#define KK2   64            // 8*8
#define PPAD  260           // padded row stride (stride%32==4 -> LDS.128 conflict-free in 8-lane phases)
#define VCHUNK 128          // v per smem chunk
#define NCHUNK 4            // 512/128
#define D1    768           // 3*CH
#define D0    320           // CH + kk

// scratch (device globals: allocation-free)
__device__ float g_inv_wn[VCN];
__device__ float g_inp[(size_t)NPAT * D0];   // 9.2 MB
__device__ float g_h1 [(size_t)NPAT * D1];   // 22.1 MB

// ---------------- packed fp32x2 helpers ----------------
__device__ __forceinline__ unsigned long long ffma2(unsigned long long a,
                                                    unsigned long long b,
                                                    unsigned long long c) {
    unsigned long long d;
    asm("fma.rn.f32x2 %0, %1, %2, %3;" : "=l"(d) : "l"(a), "l"(b), "l"(c));
    return d;
}
__device__ __forceinline__ float f2sum(unsigned long long v) {
    float lo, hi;
    asm("mov.b64 {%0, %1}, %2;" : "=f"(lo), "=f"(hi) : "l"(v));
    return lo + hi;
}

// ---------------- kernel W: inverse weight norms ----------------
__global__ void wnorm_kernel(const float* __restrict__ cw) {
    int v = threadIdx.x;                  // 512 threads, 1 block
    const float* r = cw + (size_t)v * CHN;
    float s = 0.f;
    #pragma unroll 8
    for (int c = 0; c < CHN; c++) { float w = r[c]; s += w * w; }
    g_inv_wn[v] = 1.0f / sqrtf(s);
}

// ---------------- kernel A: per-patch cosine sim + argmax + feature build ----------------
// grid = 7200 blocks, 256 threads. Dynamic smem ~202 KB.
// Main-loop mapping: warp w owns s-tile [8w, 8w+8) (register accumulators),
// lane ln owns v = chunk*128 + vh*32 + ln for vh in 0..3.
// Patch operand loads are uniform-address broadcasts (1 wavefront each);
// weight loads are lane-unique conflict-free LDS.128.
__global__ __launch_bounds__(256, 1)
void patch_kernel(const float* __restrict__ x, const float* __restrict__ cw) {
    extern __shared__ float sm[];
    float* p_sm   = sm;                         // [64][PPAD]
    float* w_sm   = sm + KK2 * PPAD;            // [128][PPAD]
    float* inv_xn = w_sm + VCHUNK * PPAD;       // [64]
    float* red_val = inv_xn + 64;               // [256]
    int*   red_idx = (int*)(red_val + 256);     // [256]

    const int t = threadIdx.x;
    const int n = blockIdx.x;
    const int b  = n / LPB;
    const int l  = n - b * LPB;
    const int oy = l / OHW;
    const int ox = l - oy * OHW;

    const float* xb = x + ((size_t)b * CHN) * (HWD * HWD) + (oy * STRD) * HWD + (ox * STRD);

    // ---- load patch: 2048 (c,kh) rows of 8 contiguous floats; 8 rows/thread ----
    #pragma unroll
    for (int i = 0; i < 8; i++) {
        int r  = t + 256 * i;
        int c  = r >> 3;
        int kh = r & 7;
        const float* src = xb + (size_t)c * (HWD * HWD) + kh * HWD;
        float* dst = p_sm + c;
        #pragma unroll
        for (int kw = 0; kw < 8; kw++)
            dst[(kh * 8 + kw) * PPAD] = src[kw];
    }
    __syncthreads();

    // ---- x_norm: 4 partial sums per s ----
    {
        int s = t & 63, part = t >> 6;
        const float* pr = p_sm + s * PPAD + part * 64;
        float a = 0.f;
        #pragma unroll 8
        for (int i = 0; i < 64; i++) { float v = pr[i]; a += v * v; }
        red_val[t] = a;
    }
    __syncthreads();
    if (t < 64) {
        float ss = red_val[t] + red_val[t + 64] + red_val[t + 128] + red_val[t + 192];
        inv_xn[t] = 1.0f / sqrtf(ss);
    }

    // ---- main streaming GEMM + argmax ----
    const int w  = t >> 5;                 // warp id -> s-tile
    const int ln = t & 31;                 // lane -> v within chunk
    const float* p_base = p_sm + (w * 8) * PPAD;
    const float* wr0    = w_sm + ln * PPAD;

    float bestv = -1e30f;
    int   besti = 0;

    for (int ch = 0; ch < NCHUNK; ch++) {
        __syncthreads();  // w_sm readers of previous chunk done; inv_xn visible on first pass
        // stage 128 x 256 weight chunk (coalesced)
        {
            const float* wsrc = cw + (size_t)(ch * VCHUNK) * CHN;
            #pragma unroll 4
            for (int i = 0; i < 128; i++) {
                int idx = t + 256 * i;           // 0..32767
                int vl = idx >> 8, c = idx & 255;
                w_sm[vl * PPAD + c] = wsrc[idx];
            }
        }
        __syncthreads();

        unsigned long long acc[8][4];
        #pragma unroll
        for (int s = 0; s < 8; s++)
            #pragma unroll
            for (int vh = 0; vh < 4; vh++) acc[s][vh] = 0ull;

        #pragma unroll 2
        for (int c = 0; c < CHN; c += 4) {
            ulonglong2 wv0 = *reinterpret_cast<const ulonglong2*>(wr0 + c);
            ulonglong2 wv1 = *reinterpret_cast<const ulonglong2*>(wr0 + 32 * PPAD + c);
            ulonglong2 wv2 = *reinterpret_cast<const ulonglong2*>(wr0 + 64 * PPAD + c);
            ulonglong2 wv3 = *reinterpret_cast<const ulonglong2*>(wr0 + 96 * PPAD + c);
            #pragma unroll
            for (int s = 0; s < 8; s++) {
                ulonglong2 pv = *reinterpret_cast<const ulonglong2*>(p_base + s * PPAD + c); // broadcast
                acc[s][0] = ffma2(pv.x, wv0.x, acc[s][0]);
                acc[s][0] = ffma2(pv.y, wv0.y, acc[s][0]);
                acc[s][1] = ffma2(pv.x, wv1.x, acc[s][1]);
                acc[s][1] = ffma2(pv.y, wv1.y, acc[s][1]);
                acc[s][2] = ffma2(pv.x, wv2.x, acc[s][2]);
                acc[s][2] = ffma2(pv.y, wv2.y, acc[s][2]);
                acc[s][3] = ffma2(pv.x, wv3.x, acc[s][3]);
                acc[s][3] = ffma2(pv.y, wv3.y, acc[s][3]);
            }
        }

        #pragma unroll
        for (int vh = 0; vh < 4; vh++) {
            int v = ch * VCHUNK + vh * 32 + ln;
            float iw = g_inv_wn[v];
            #pragma unroll
            for (int s = 0; s < 8; s++) {
                int sg = w * 8 + s;
                float y = f2sum(acc[s][vh]) * inv_xn[sg] * iw;
                int gi = v * KK2 + sg;
                if (y > bestv || (y == bestv && gi < besti)) { bestv = y; besti = gi; }
            }
        }
    }

    // ---- block argmax reduction (tie -> smallest idx, matches jnp.argmax) ----
    __syncthreads();
    red_val[t] = bestv; red_idx[t] = besti;
    __syncthreads();
    #pragma unroll
    for (int off = 128; off > 0; off >>= 1) {
        if (t < off) {
            float v2 = red_val[t + off]; int i2 = red_idx[t + off];
            if (v2 > red_val[t] || (v2 == red_val[t] && i2 < red_idx[t])) {
                red_val[t] = v2; red_idx[t] = i2;
            }
        }
        __syncthreads();
    }
    const float max_sim = red_val[0];
    const int   idx     = red_idx[0];
    const int   max_ch  = idx >> 6;
    const int   col     = idx & 63;

    // ---- sim_map_max: recompute y[max_ch][s] for all s ----
    float partial;
    {
        int s = t & 63, part = t >> 6;
        const float* pr = p_sm + s * PPAD + part * 64;
        const float* wr = cw + (size_t)max_ch * CHN + part * 64;
        float a = 0.f;
        #pragma unroll 8
        for (int i = 0; i < 64; i++) a += pr[i] * wr[i];
        partial = a;
    }
    __syncthreads();           // everyone has read red_val[0]/red_idx[0]
    red_val[t] = partial;
    __syncthreads();

    float* inp_row = g_inp + (size_t)n * D0;
    const float iwmax = g_inv_wn[max_ch];
    if (t < 64) {
        float d = red_val[t] + red_val[t + 64] + red_val[t + 128] + red_val[t + 192];
        inp_row[CHN + t] = d * inv_xn[t] * iwmax;
    }

    // ---- integ: max_act * max_sim + w[max_ch] * (1 - max_sim) ----
    {
        float pa = p_sm[col * PPAD + t];                  // t == channel
        float wv = cw[(size_t)max_ch * CHN + t];
        inp_row[t] = pa * max_sim + wv * (1.0f - max_sim);
    }
}

// ---------------- tiled SGEMM for the MLP: C = act(A * B^T + bias) ----------------
// A: [M][KD] row-major, B: [NC][KD] row-major (so inner product of rows).
// Block tile 64x64, thread micro-tile 4x4, 256 threads.
template <int KD, int ACT>
__device__ __forceinline__ void gemm_body(const float* __restrict__ A,
                                          const float* __restrict__ B,
                                          const float* __restrict__ bias,
                                          float* __restrict__ C,
                                          int M, int NC) {
    __shared__ float As[32][68];
    __shared__ float Bs[32][68];
    const int t  = threadIdx.x;
    const int tx = t & 15;     // n
    const int ty = t >> 4;     // m
    const int m0 = blockIdx.x * 64;
    const int n0 = blockIdx.y * 64;

    float acc[4][4] = {};

    for (int k0 = 0; k0 < KD; k0 += 32) {
        #pragma unroll
        for (int i = 0; i < 8; i++) {
            int e  = t + 256 * i;
            int mr = e >> 5, kc = e & 31;
            int mg = m0 + mr;
            As[kc][mr] = (mg < M) ? A[(size_t)mg * KD + k0 + kc] : 0.0f;
            int og = n0 + mr;                         // N tiles always divide
            Bs[kc][mr] = B[(size_t)og * KD + k0 + kc];
        }
        __syncthreads();
        #pragma unroll 8
        for (int kk = 0; kk < 32; kk++) {
            float4 av = *reinterpret_cast<const float4*>(&As[kk][ty * 4]);
            float4 bv = *reinterpret_cast<const float4*>(&Bs[kk][tx * 4]);
            float a[4] = {av.x, av.y, av.z, av.w};
            float bb[4] = {bv.x, bv.y, bv.z, bv.w};
            #pragma unroll
            for (int i = 0; i < 4; i++)
                #pragma unroll
                for (int j = 0; j < 4; j++)
                    acc[i][j] += a[i] * bb[j];
        }
        __syncthreads();
    }

    #pragma unroll
    for (int i = 0; i < 4; i++) {
        int mg = m0 + ty * 4 + i;
        if (mg >= M) continue;
        #pragma unroll
        for (int j = 0; j < 4; j++) {
            int og = n0 + tx * 4 + j;
            float v = acc[i][j] + bias[og];
            if (ACT == 0) v = (v > 0.f) ? v : 0.2f * v;     // leaky relu
            else          v = tanhf(v);
            C[(size_t)mg * NC + og] = v;
        }
    }
}

__global__ __launch_bounds__(256)
void gemm1_kernel(const float* __restrict__ W1, const float* __restrict__ b1) {
    gemm_body<D0, 0>(g_inp, W1, b1, g_h1, NPAT, D1);
}

__global__ __launch_bounds__(256)
void gemm2_kernel(const float* __restrict__ W2, const float* __restrict__ b2,
                  float* __restrict__ out) {
    gemm_body<D1, 1>(g_h1, W2, b2, out, NPAT, CHN);
}

// ---------------- launch ----------------
extern "C" void kernel_launch(void* const* d_in, const int* in_sizes, int n_in,
                              void* d_out, int out_size) {
    const float* x   = (const float*)d_in[0];
    const float* cw  = (const float*)d_in[1];
    const float* W1  = (const float*)d_in[2];
    const float* b1  = (const float*)d_in[3];
    const float* W2  = (const float*)d_in[4];
    const float* b2  = (const float*)d_in[5];
    float* out = (float*)d_out;

    const int smemA = (KK2 * PPAD + VCHUNK * PPAD + 64 + 256 + 256 + 8) * 4;  // ~202 KB
    cudaFuncSetAttribute(patch_kernel, cudaFuncAttributeMaxDynamicSharedMemorySize, smemA);

    wnorm_kernel<<<1, VCN>>>(cw);
    patch_kernel<<<NPAT, 256, smemA>>>(x, cw);
    gemm1_kernel<<<dim3((NPAT + 63) / 64, D1 / 64), 256>>>(W1, b1);
    gemm2_kernel<<<dim3((NPAT + 63) / 64, CHN / 64), 256>>>(W2, b2, out);
}